// round 17
// baseline (speedup 1.0000x reference)
#include <cuda_runtime.h>

#define T_STEPS 2048
#define OUT_DIM 8
#define BATCH 512

typedef unsigned long long ull;

// staging for precomputed layer-1 input projection, layout [b][t][unit*4+gate]
__device__ float g_xg[(size_t)BATCH * T_STEPS * 128];

// ---- packed fp32x2 helpers (sm_100+) ----
__device__ __forceinline__ void fma2(ull &d, ull a, ull b) {
    asm("fma.rn.f32x2 %0, %1, %2, %0;" : "+l"(d) : "l"(a), "l"(b));
}
__device__ __forceinline__ ull add2(ull a, ull b) {
    ull r; asm("add.rn.f32x2 %0, %1, %2;" : "=l"(r) : "l"(a), "l"(b)); return r;
}
__device__ __forceinline__ float red2(ull a) {
    float lo, hi;
    asm("mov.b64 {%0,%1}, %2;" : "=f"(lo), "=f"(hi) : "l"(a));
    return lo + hi;
}
__device__ __forceinline__ void lds2(ull &a, ull &b, unsigned addr) {
    asm volatile("ld.shared.v2.b64 {%0,%1}, [%2];" : "=l"(a), "=l"(b) : "r"(addr));
}

// ---- fast activations via hardware tanh (single MUFU op) ----
__device__ __forceinline__ float tanha(float x) {
    float r; asm("tanh.approx.f32 %0, %1;" : "=f"(r) : "f"(x)); return r;
}
__device__ __forceinline__ float sigm(float x) {
    return fmaf(0.5f, tanha(0.5f * x), 0.5f);
}

// =====================================================================
// prepass (R7 form, measured 258us): g_xg[b][t][ch] =
//   (bih0+bhh0)[r] + Wih0[r,:].x[b,t,:],  r=(ch&3)*32+(ch>>2), ch=4u+gate
// grid 512 (=b), block 128: thread j owns channel j.
// =====================================================================
__global__ void __launch_bounds__(128) xg_prepass(
    const float *__restrict__ X, const float *__restrict__ Wih0,
    const float *__restrict__ bih0, const float *__restrict__ bhh0)
{
    __shared__ __align__(16) float xt[32 * 32];   // 32 timesteps x 32 features
    const int j = threadIdx.x;
    const int b = blockIdx.x;
    const int r = (j & 3) * 32 + (j >> 2);

    ull w[16];
    {
        const ull *p = (const ull *)(Wih0 + r * 32);
#pragma unroll
        for (int i = 0; i < 16; i++) w[i] = p[i];
    }
    const float bias = bih0[r] + bhh0[r];

    const float *xb = X + (size_t)b * T_STEPS * 32;
    float *outp = g_xg + (size_t)b * T_STEPS * 128;
    const unsigned xtb = (unsigned)__cvta_generic_to_shared(xt);

    for (int tt = 0; tt < T_STEPS; tt += 32) {
        __syncthreads();
        const float4 *src = (const float4 *)(xb + tt * 32);
        float4 *dst4 = (float4 *)xt;
        dst4[j] = src[j];
        dst4[j + 128] = src[j + 128];
        __syncthreads();

#pragma unroll 4
        for (int t = 0; t < 32; t++) {
            ull a0 = 0ull, a1 = 0ull;
#pragma unroll
            for (int i = 0; i < 4; i++) {
                ull p0, p1, p2, p3;
                lds2(p0, p1, xtb + (unsigned)(t * 128 + i * 32));
                lds2(p2, p3, xtb + (unsigned)(t * 128 + i * 32 + 16));
                fma2(a0, w[4 * i + 0], p0); fma2(a1, w[4 * i + 1], p1);
                fma2(a0, w[4 * i + 2], p2); fma2(a1, w[4 * i + 3], p3);
            }
            outp[(size_t)(tt + t) * 128 + j] = red2(add2(a0, a1)) + bias;
        }
    }
}

// =====================================================================
// recurrent kernel: 64 threads = 1 batch (R15 base, measured best).
// warp 0: gate rows {i,f}; warp 1: {g,o}. 2 rows/lane, both layers.
// NEW vs R15: Whh1.h2(t-1) dot moved into window B (h2 stable there;
// accumulators reuse phase-A registers -> register-neutral).
// =====================================================================
__global__ void __launch_bounds__(64, 4) lstm_rec(
    const float *__restrict__ Whh0,
    const float *__restrict__ Wih1, const float *__restrict__ Whh1,
    const float *__restrict__ bih1, const float *__restrict__ bhh1,
    const float *__restrict__ Wfc, const float *__restrict__ bfc,
    float *__restrict__ out)
{
    __shared__ __align__(16) float h1s[32];
    __shared__ __align__(16) float h2s[32];
    __shared__ __align__(16) float xb0[32];
    __shared__ __align__(16) float xb1[32];

    const int tid = threadIdx.x;
    const int b = blockIdx.x;
    const int w = tid >> 5;           // 0: gates i,f   1: gates g,o
    const int u = tid & 31;           // hidden unit
    const int rA = (2 * w) * 32 + u;  // first owned gate row
    const int rB = rA + 32;           // second owned gate row

    // ---- register-resident weights: 6 rows x 32 = 96 ull = 192 regs ----
    ull wh0A[16], wh0B[16], wi1A[16], wi1B[16], wh1A[16], wh1B[16];
    {
        const ull *p;
        p = (const ull *)(Whh0 + rA * 32);
#pragma unroll
        for (int i = 0; i < 16; i++) wh0A[i] = p[i];
        p = (const ull *)(Whh0 + rB * 32);
#pragma unroll
        for (int i = 0; i < 16; i++) wh0B[i] = p[i];
        p = (const ull *)(Wih1 + rA * 32);
#pragma unroll
        for (int i = 0; i < 16; i++) wi1A[i] = p[i];
        p = (const ull *)(Wih1 + rB * 32);
#pragma unroll
        for (int i = 0; i < 16; i++) wi1B[i] = p[i];
        p = (const ull *)(Whh1 + rA * 32);
#pragma unroll
        for (int i = 0; i < 16; i++) wh1A[i] = p[i];
        p = (const ull *)(Whh1 + rB * 32);
#pragma unroll
        for (int i = 0; i < 16; i++) wh1B[i] = p[i];
    }
    const float b2A = bih1[rA] + bhh1[rA];
    const float b2B = bih1[rB] + bhh1[rB];

    // xg stream: float4 per (t, u) covering channels 4u..4u+3
    const float4 *xgp = (const float4 *)(g_xg + (size_t)b * T_STEPS * 128) + u;
    float4 cur = __ldg(xgp);
    float4 nxt = __ldg(xgp + 32);

    if (tid < 32) { h1s[tid] = 0.0f; h2s[tid] = 0.0f; }
    float c = 0.0f;                   // warp0: c1   warp1: c2

    const unsigned h1b = (unsigned)__cvta_generic_to_shared(h1s);
    const unsigned h2b = (unsigned)__cvta_generic_to_shared(h2s);
    __syncthreads();

#pragma unroll 1
    for (int t = 0; t < T_STEPS; t++) {
        // prefetch xg(t+2)
        float4 pre;
        {
            int tf = t + 2; if (tf > T_STEPS - 1) tf = T_STEPS - 1;
            pre = __ldg(xgp + (size_t)tf * 32);
        }

        // ===== phase A: layer-1 gates (rows rA,rB over h1(t-1)) =====
        ull a0 = 0ull, a1 = 0ull, d0 = 0ull, d1 = 0ull;
#pragma unroll
        for (int i = 0; i < 4; i++) {
            ull p0, p1, p2, p3;
            lds2(p0, p1, h1b + (unsigned)(i * 32));
            lds2(p2, p3, h1b + (unsigned)(i * 32 + 16));
            fma2(a0, wh0A[4 * i + 0], p0); fma2(a1, wh0A[4 * i + 1], p1);
            fma2(a0, wh0A[4 * i + 2], p2); fma2(a1, wh0A[4 * i + 3], p3);
            fma2(d0, wh0B[4 * i + 0], p0); fma2(d1, wh0B[4 * i + 1], p1);
            fma2(d0, wh0B[4 * i + 2], p2); fma2(d1, wh0B[4 * i + 3], p3);
        }
        float g0 = red2(add2(a0, a1)) + (w ? cur.z : cur.x);
        float g1 = red2(add2(d0, d1)) + (w ? cur.w : cur.y);
        float act0 = w ? tanha(g0) : sigm(g0);   // w0: i     w1: g
        float act1 = sigm(g1);                   // w0: f     w1: o
        if (w) { xb0[u] = act0; xb1[u] = act1; }
        __syncthreads();                         // bar 1

        // ===== window B: w0 updates c1/h1; BOTH warps run the
        //       Whh1 . h2(t-1) dot (h2 stable; regs reused from A) =====
        if (!w) {
            float vg = xb0[u], vo = xb1[u];
            c = fmaf(act1, c, act0 * vg);        // c1 = f*c1 + i*g
            h1s[u] = vo * tanha(c);
        }
        a0 = 0ull; a1 = 0ull; d0 = 0ull; d1 = 0ull;
#pragma unroll
        for (int i = 0; i < 4; i++) {
            ull p0, p1, p2, p3;
            lds2(p0, p1, h2b + (unsigned)(i * 32));
            lds2(p2, p3, h2b + (unsigned)(i * 32 + 16));
            fma2(a0, wh1A[4 * i + 0], p0); fma2(a1, wh1A[4 * i + 1], p1);
            fma2(a0, wh1A[4 * i + 2], p2); fma2(a1, wh1A[4 * i + 3], p3);
            fma2(d0, wh1B[4 * i + 0], p0); fma2(d1, wh1B[4 * i + 1], p1);
            fma2(d0, wh1B[4 * i + 2], p2); fma2(d1, wh1B[4 * i + 3], p3);
        }
        __syncthreads();                         // bar 2

        // ===== phase C: add Wih1 . h1(t); finish layer-2 gates =====
#pragma unroll
        for (int i = 0; i < 4; i++) {
            ull p0, p1, p2, p3;
            lds2(p0, p1, h1b + (unsigned)(i * 32));
            lds2(p2, p3, h1b + (unsigned)(i * 32 + 16));
            fma2(a0, wi1A[4 * i + 0], p0); fma2(a1, wi1A[4 * i + 1], p1);
            fma2(a0, wi1A[4 * i + 2], p2); fma2(a1, wi1A[4 * i + 3], p3);
            fma2(d0, wi1B[4 * i + 0], p0); fma2(d1, wi1B[4 * i + 1], p1);
            fma2(d0, wi1B[4 * i + 2], p2); fma2(d1, wi1B[4 * i + 3], p3);
        }
        g0 = red2(add2(a0, a1)) + b2A;
        g1 = red2(add2(d0, d1)) + b2B;
        act0 = w ? tanha(g0) : sigm(g0);
        act1 = sigm(g1);
        if (!w) { xb0[u] = act0; xb1[u] = act1; }
        __syncthreads();                         // bar 3

        // ===== phase D (warp 1): c2/h2 update =====
        if (w) {
            float vi = xb0[u], vf = xb1[u];
            c = fmaf(vf, c, vi * act0);          // c2 = f*c2 + i*g
            h2s[u] = act1 * tanha(c);
        }
        // next step's bar 1 makes h2s/xb visible before their next use

        cur = nxt; nxt = pre;
    }
    __syncthreads();

    // ===== FC head on h2(T-1) =====
    if (tid < OUT_DIM) {
        float s = bfc[tid];
        const float *wf = Wfc + tid * 32;
#pragma unroll
        for (int k = 0; k < 32; k++) s = fmaf(wf[k], h2s[k], s);
        out[b * OUT_DIM + tid] = s;
    }
}

extern "C" void kernel_launch(void* const* d_in, const int* in_sizes, int n_in,
                              void* d_out, int out_size) {
    (void)in_sizes; (void)n_in; (void)out_size;
    const float *X    = (const float *)d_in[0];
    const float *Wih0 = (const float *)d_in[1];
    const float *Whh0 = (const float *)d_in[2];
    const float *bih0 = (const float *)d_in[3];
    const float *bhh0 = (const float *)d_in[4];
    const float *Wih1 = (const float *)d_in[5];
    const float *Whh1 = (const float *)d_in[6];
    const float *bih1 = (const float *)d_in[7];
    const float *bhh1 = (const float *)d_in[8];
    const float *Wfc  = (const float *)d_in[9];
    const float *bfc  = (const float *)d_in[10];

    xg_prepass<<<BATCH, 128>>>(X, Wih0, bih0, bhh0);
    lstm_rec<<<BATCH, 64>>>(Whh0, Wih1, Whh1, bih1, bhh1, Wfc, bfc,
                            (float *)d_out);
}